// round 7
// baseline (speedup 1.0000x reference)
#include <cuda_runtime.h>
#include <cuda_fp16.h>
#include <cstdint>

#define B 16
#define C 256
#define O_CH 256
#define H 128
#define W 128
#define G 32
#define CG 8
#define OG 8
#define HW (H*W)

#define CB 4               // batches per pipeline chunk
#define NCHUNK (B/CB)      // 4
#define CONV_BLOCKS 1024   // 8 strips * 32 groups * CB
#define STAT_BLOCKS 1024   // CB * C

#define RSTRIP 16
#define TROWS (RSTRIP+2)   // 18 staged rows
#define TC 132             // padded cols
#define NTASK (TROWS*16)   // 288 staging tasks

__device__ float d_mean[B*C];
__device__ float d_inv[B*C];

__device__ __forceinline__ uint32_t pkh2(float a, float b) {
    __half2 h = __floats2half2_rn(a, b);
    return *reinterpret_cast<uint32_t*>(&h);
}
__device__ __forceinline__ uint32_t smem_u32(const void* p) {
    uint32_t a;
    asm("{ .reg .u64 t; cvta.to.shared.u64 t, %1; cvt.u32.u64 %0, t; }" : "=r"(a) : "l"(p));
    return a;
}
__device__ __forceinline__ uint32_t SW(uint32_t a16) { return a16 ^ ((a16 >> 3) & 7u); }
__device__ __forceinline__ void sts128(uint32_t addr, uint32_t a, uint32_t b, uint32_t c, uint32_t d) {
    asm volatile("st.shared.v4.b32 [%0], {%1,%2,%3,%4};" :: "r"(addr), "r"(a), "r"(b), "r"(c), "r"(d) : "memory");
}

// ---------------------------------------------------------------------------
// Fused pipeline kernel. Even blocks: conv for chunk conv_chunk (if >=0).
// Odd blocks: instance-norm stats for chunk stats_chunk (if >=0).
// Stats(k) runs concurrently with conv(k-1) inside one launch.
// ---------------------------------------------------------------------------
__global__ __launch_bounds__(512, 2) void fused_kernel(
    const float* __restrict__ x,
    const float* __restrict__ dw,
    const float* __restrict__ pw,
    const float* __restrict__ biases,
    float* __restrict__ out,
    int conv_chunk, int stats_chunk)
{
    __shared__ __align__(16) __half tile[TROWS*TC*CG];   // 38016 B
    __shared__ float wsm[OG*72];
    __shared__ float smean[CG], sinv[CG], sbias[OG];
    __shared__ float r_s[16], r_q[16];

    int tid = threadIdx.x;
    int role, idx;
    if (conv_chunk >= 0 && stats_chunk >= 0) { role = blockIdx.x & 1; idx = blockIdx.x >> 1; }
    else if (conv_chunk >= 0)                { role = 0; idx = blockIdx.x; }
    else                                     { role = 1; idx = blockIdx.x; }

    if (role == 1) {
        // ================= stats =================
        int bc = stats_chunk * CB * C + idx;
        const float4* p = (const float4*)(x + (size_t)bc * HW);
        float s0 = 0.f, s1 = 0.f, q0 = 0.f, q1 = 0.f;
        #pragma unroll
        for (int i = tid; i < HW/8; i += 512) {
            float4 a = p[i];
            float4 b2 = p[i + HW/8];
            s0 += a.x + a.y + a.z + a.w;
            q0 += a.x*a.x + a.y*a.y + a.z*a.z + a.w*a.w;
            s1 += b2.x + b2.y + b2.z + b2.w;
            q1 += b2.x*b2.x + b2.y*b2.y + b2.z*b2.z + b2.w*b2.w;
        }
        float s = s0 + s1, ss = q0 + q1;
        #pragma unroll
        for (int o = 16; o > 0; o >>= 1) {
            s  += __shfl_down_sync(0xffffffffu, s,  o);
            ss += __shfl_down_sync(0xffffffffu, ss, o);
        }
        int lane = tid & 31, w = tid >> 5;
        if (lane == 0) { r_s[w] = s; r_q[w] = ss; }
        __syncthreads();
        if (tid == 0) {
            float S = 0.f, SS = 0.f;
            #pragma unroll
            for (int k = 0; k < 16; k++) { S += r_s[k]; SS += r_q[k]; }
            float mean = S * (1.0f / HW);
            float var  = (SS - S * mean) * (1.0f / (HW - 1));
            var = fmaxf(var, 0.0f);
            d_mean[bc] = mean;
            d_inv[bc]  = 1.0f / (sqrtf(var) + 1e-7f);
        }
        return;
    }

    // ================= conv =================
    int strip = idx & 7;
    int g     = (idx >> 3) & 31;
    int b     = conv_chunk * CB + (idx >> 8);
    int r0    = strip * RSTRIP;
    int lane  = tid & 31;
    int wi    = tid >> 5;
    uint32_t sb = smem_u32(tile);

    if (tid < CG) {
        smean[tid] = d_mean[b*C + g*CG + tid];
        sinv[tid]  = d_inv [b*C + g*CG + tid];
    }
    __syncthreads();

    // ---- fold 1x1 conv + instance norm into 3x3 weights (per-CTA) ----
    for (int t = tid; t < OG*72; t += 512) {
        int o = t / 72, it = t % 72, i = it / 9, tap = it % 9;
        const float* pwp = pw + (size_t)(b*O_CH + g*OG + o) * OG;
        float acc = 0.f;
        #pragma unroll
        for (int ip = 0; ip < 8; ip++)
            acc += pwp[ip] * dw[(((size_t)b*O_CH + (g*OG + ip))*CG + i)*9 + tap];
        wsm[t] = acc * sinv[i];
    }

    // ---- staging: task = 8 px x 8 ch -> transpose -> 8 STS.128 ----
    if (tid < NTASK) {
        int row = tid >> 4;
        int w0  = (tid & 15) << 3;
        int grow = r0 - 1 + row;
        uint32_t h[CG][4];
        if ((unsigned)grow < (unsigned)H) {
            const float* xb = x + (size_t)(b*C + g*CG) * HW + (size_t)grow * W + w0;
            #pragma unroll
            for (int ch = 0; ch < CG; ch++) {
                const float4* p = (const float4*)(xb + (size_t)ch * HW);
                float4 A0 = p[0], A1 = p[1];
                h[ch][0] = pkh2(A0.x, A0.y);
                h[ch][1] = pkh2(A0.z, A0.w);
                h[ch][2] = pkh2(A1.x, A1.y);
                h[ch][3] = pkh2(A1.z, A1.w);
            }
        } else {
            #pragma unroll
            for (int ch = 0; ch < CG; ch++) {
                uint32_t mm = pkh2(smean[ch], smean[ch]);
                h[ch][0] = mm; h[ch][1] = mm; h[ch][2] = mm; h[ch][3] = mm;
            }
        }
        #pragma unroll
        for (int p = 0; p < 8; p++) {
            uint32_t sel = (p & 1) ? 0x7632u : 0x5410u;
            int i2 = p >> 1;
            uint32_t q0 = __byte_perm(h[0][i2], h[1][i2], sel);
            uint32_t q1 = __byte_perm(h[2][i2], h[3][i2], sel);
            uint32_t q2 = __byte_perm(h[4][i2], h[5][i2], sel);
            uint32_t q3 = __byte_perm(h[6][i2], h[7][i2], sel);
            uint32_t a16 = (uint32_t)(row*TC + w0 + 1 + p);
            sts128(sb + SW(a16)*16u, q0, q1, q2, q3);
        }
    } else if (tid < NTASK + 36) {
        int idx2 = tid - NTASK;
        int row = idx2 >> 1;
        int col = (idx2 & 1) ? 129 : 0;
        uint32_t q0 = pkh2(smean[0], smean[1]);
        uint32_t q1 = pkh2(smean[2], smean[3]);
        uint32_t q2 = pkh2(smean[4], smean[5]);
        uint32_t q3 = pkh2(smean[6], smean[7]);
        uint32_t a16 = (uint32_t)(row*TC + col);
        sts128(sb + SW(a16)*16u, q0, q1, q2, q3);
    }
    __syncthreads();

    // ---- bias fold: bias' = bias - sum W'*mean ----
    if (tid < OG) {
        float s = 0.f;
        #pragma unroll
        for (int k = 0; k < 72; k++) s += wsm[tid*72 + k] * smean[k/9];
        sbias[tid] = biases[b*O_CH + g*OG + tid] - s;
    }
    __syncthreads();

    // ---- B fragments (weights) ----
    int gid = lane >> 2;
    int tg  = lane & 3;
    uint32_t bf[9];
    {
        const float* wn = wsm + gid * 72 + (tg * 2) * 9;
        #pragma unroll
        for (int j = 0; j < 4; j++) {
            bf[2*j + 0] = pkh2(wn[2*j],     wn[9 + 2*j]);
            bf[2*j + 1] = pkh2(wn[2*j + 1], wn[9 + 2*j + 1]);
        }
        bf[8] = pkh2(wn[8], wn[17]);
    }

    // ---- per-thread ldmatrix base offsets ----
    int q  = lane >> 3;
    int l8 = lane & 7;
    int base_j[4], base_8;
    #pragma unroll
    for (int j = 0; j < 4; j++) {
        int t = 2*j + (q >> 1);
        base_j[j] = (wi + t/3)*TC + (q & 1)*8 + l8 + (t % 3);
    }
    base_8 = (wi + 2)*TC + (q & 1)*8 + l8 + 2;

    float bia0 = sbias[tg*2];
    float bia1 = sbias[tg*2 + 1];

    int hrow = r0 + wi;
    float* obase = out + (size_t)(b*O_CH + g*OG + tg*2) * HW + (size_t)hrow * W;

    #pragma unroll
    for (int ws = 0; ws < 8; ws++) {
        int w16 = ws * 16;
        float d0 = 0.f, d1 = 0.f, d2 = 0.f, d3 = 0.f;

        #pragma unroll
        for (int j = 0; j < 4; j++) {
            uint32_t a16 = (uint32_t)(base_j[j] + w16);
            uint32_t addr = sb + SW(a16)*16u;
            uint32_t a0, a1, a2, a3;
            asm volatile("ldmatrix.sync.aligned.m8n8.x4.shared.b16 {%0,%1,%2,%3}, [%4];"
                         : "=r"(a0), "=r"(a1), "=r"(a2), "=r"(a3) : "r"(addr));
            asm volatile(
                "mma.sync.aligned.m16n8k16.row.col.f32.f16.f16.f32 "
                "{%0,%1,%2,%3},{%4,%5,%6,%7},{%8,%9},{%0,%1,%2,%3};"
                : "+f"(d0), "+f"(d1), "+f"(d2), "+f"(d3)
                : "r"(a0), "r"(a1), "r"(a2), "r"(a3),
                  "r"(bf[2*j]), "r"(bf[2*j + 1]));
        }
        {
            uint32_t a16 = (uint32_t)(base_8 + w16);
            uint32_t addr = sb + SW(a16)*16u;
            uint32_t a0, a1;
            asm volatile("ldmatrix.sync.aligned.m8n8.x2.shared.b16 {%0,%1}, [%2];"
                         : "=r"(a0), "=r"(a1) : "r"(addr));
            asm volatile(
                "mma.sync.aligned.m16n8k8.row.col.f32.f16.f16.f32 "
                "{%0,%1,%2,%3},{%4,%5},{%6},{%0,%1,%2,%3};"
                : "+f"(d0), "+f"(d1), "+f"(d2), "+f"(d3)
                : "r"(a0), "r"(a1), "r"(bf[8]));
        }

        float* ob = obase + w16 + gid;
        ob[0]      = d0 + bia0;
        ob[HW]     = d1 + bia1;
        ob[8]      = d2 + bia0;
        ob[HW + 8] = d3 + bia1;
    }
}

// ---------------------------------------------------------------------------
extern "C" void kernel_launch(void* const* d_in, const int* in_sizes, int n_in,
                              void* d_out, int out_size) {
    const float* x      = (const float*)d_in[0];
    const float* dw     = (const float*)d_in[1];
    const float* pw     = (const float*)d_in[2];
    const float* biases = (const float*)d_in[3];
    float* out = (float*)d_out;

    // software pipeline: stats(c0) | conv(c0)+stats(c1) | ... | conv(c3)
    fused_kernel<<<STAT_BLOCKS, 512>>>(x, dw, pw, biases, out, -1, 0);
    for (int k = 1; k < NCHUNK; k++)
        fused_kernel<<<CONV_BLOCKS + STAT_BLOCKS, 512>>>(x, dw, pw, biases, out, k - 1, k);
    fused_kernel<<<CONV_BLOCKS, 512>>>(x, dw, pw, biases, out, NCHUNK - 1, -1);
}

// round 8
// speedup vs baseline: 1.0092x; 1.0092x over previous
#include <cuda_runtime.h>
#include <cuda_fp16.h>
#include <cstdint>

#define B 16
#define C 256
#define O_CH 256
#define H 128
#define W 128
#define G 32
#define CG 8
#define OG 8
#define HW (H*W)

#define RSTRIP 16
#define TROWS (RSTRIP+2)   // 18 staged rows
#define TC 132             // cols: 0=left pad, 1..128 px, 129=right pad, 130/131 unused
#define SLAB (130*132)     // uint4 entries per (b,g): 130 stored rows x 132 cols

__device__ float d_mean[B*C];
__device__ float d_inv[B*C];
__device__ float d_comb[B*O_CH*CG*9];   // norm-folded weights W' = W*inv
__device__ float d_bias2[B*O_CH];       // bias' = bias - sum W'*mean
__device__ uint4 d_xh[B*G*SLAB];        // fp16 x, pixel-major [row][col][8ch], ~140MB

__device__ __forceinline__ uint32_t pkh2(float a, float b) {
    __half2 h = __floats2half2_rn(a, b);
    return *reinterpret_cast<uint32_t*>(&h);
}
__device__ __forceinline__ uint32_t smem_u32(const void* p) {
    uint32_t a;
    asm("{ .reg .u64 t; cvta.to.shared.u64 t, %1; cvt.u32.u64 %0, t; }" : "=r"(a) : "l"(p));
    return a;
}
__device__ __forceinline__ uint32_t SW(uint32_t a16) { return a16 ^ ((a16 >> 3) & 7u); }
__device__ __forceinline__ void sts128(uint32_t addr, uint32_t a, uint32_t b, uint32_t c, uint32_t d) {
    asm volatile("st.shared.v4.b32 [%0], {%1,%2,%3,%4};" :: "r"(addr), "r"(a), "r"(b), "r"(c), "r"(d) : "memory");
}

// ---------------------------------------------------------------------------
// Kernel 1: per-(b,g) fused stats + fp16 transpose-convert.
// One read of x: accumulates per-channel (s,ss) AND writes raw fp16 pixel-major.
// Borders written as mean (=> normalized contribution 0 under folded weights).
// ---------------------------------------------------------------------------
__global__ __launch_bounds__(512) void transform_kernel(const float* __restrict__ x) {
    __shared__ float rs[16][16];     // [warp][8 s + 8 ss]
    __shared__ uint4 smeanpack;

    int bg  = blockIdx.x;            // b*G + g
    int b   = bg >> 5;
    int g   = bg & 31;
    int tid = threadIdx.x;
    int lane = tid & 31, wid = tid >> 5;

    const float* xb = x + (size_t)(b*C + g*CG) * HW;
    uint4* slab = d_xh + (size_t)bg * SLAB;

    float s[CG], ss[CG];
    #pragma unroll
    for (int c = 0; c < CG; c++) { s[c] = 0.f; ss[c] = 0.f; }

    // interior: convert + accumulate (one pass over x)
    for (int px = tid; px < HW; px += 512) {
        int row = px >> 7, col = px & 127;
        float v[CG];
        #pragma unroll
        for (int c = 0; c < CG; c++) {
            float t = xb[(size_t)c*HW + px];
            v[c] = t;
            s[c] += t;
            ss[c] = fmaf(t, t, ss[c]);
        }
        uint4 pkt = make_uint4(pkh2(v[0], v[1]), pkh2(v[2], v[3]),
                               pkh2(v[4], v[5]), pkh2(v[6], v[7]));
        slab[(row + 1)*TC + (col + 1)] = pkt;
    }

    // warp reduce 16 accumulators
    #pragma unroll
    for (int c = 0; c < CG; c++) {
        #pragma unroll
        for (int o = 16; o > 0; o >>= 1) {
            s[c]  += __shfl_down_sync(0xffffffffu, s[c],  o);
            ss[c] += __shfl_down_sync(0xffffffffu, ss[c], o);
        }
    }
    if (lane == 0) {
        #pragma unroll
        for (int c = 0; c < CG; c++) { rs[wid][c] = s[c]; rs[wid][8 + c] = ss[c]; }
    }
    __syncthreads();

    __shared__ float smean[CG];
    if (tid < CG) {
        float S = 0.f, SS = 0.f;
        #pragma unroll
        for (int w = 0; w < 16; w++) { S += rs[w][tid]; SS += rs[w][8 + tid]; }
        float mean = S * (1.0f / HW);
        float var  = (SS - S * mean) * (1.0f / (HW - 1));
        var = fmaxf(var, 0.0f);
        d_mean[b*C + g*CG + tid] = mean;
        d_inv [b*C + g*CG + tid] = 1.0f / (sqrtf(var) + 1e-7f);
        smean[tid] = mean;
    }
    __syncthreads();
    if (tid == 0)
        smeanpack = make_uint4(pkh2(smean[0], smean[1]), pkh2(smean[2], smean[3]),
                               pkh2(smean[4], smean[5]), pkh2(smean[6], smean[7]));
    __syncthreads();

    // borders: rows 0 & 129 (full 132 cols), cols 0 & 129 (rows 1..128)
    uint4 mp = smeanpack;
    for (int i = tid; i < TC; i += 512) { slab[i] = mp; slab[129*TC + i] = mp; }
    for (int r = 1 + tid; r <= 128; r += 512) { slab[r*TC] = mp; slab[r*TC + 129] = mp; }
}

// ---------------------------------------------------------------------------
// Kernel 2: fold 1x1 conv AND instance-norm into 3x3 weights + bias.
// ---------------------------------------------------------------------------
__global__ void combine_kernel(const float* __restrict__ dw,
                               const float* __restrict__ pw,
                               const float* __restrict__ biases) {
    __shared__ float red[72];
    int bo = blockIdx.x;
    int t  = threadIdx.x;          // 0..71
    int o  = bo % O_CH;
    int b  = bo / O_CH;
    int g  = o >> 3;
    int i  = t / 9, tap = t % 9;
    const float* pwp = pw + (size_t)bo * OG;
    float acc = 0.f;
    #pragma unroll
    for (int ip = 0; ip < 8; ip++)
        acc += pwp[ip] * dw[(((size_t)b*O_CH + (g*OG + ip))*CG + i)*9 + tap];
    float inv_i  = d_inv [b*C + g*CG + i];
    float mean_i = d_mean[b*C + g*CG + i];
    float wp = acc * inv_i;
    d_comb[(size_t)bo*72 + t] = wp;
    red[t] = wp * mean_i;
    __syncthreads();
    if (t == 0) {
        float s = 0.f;
        #pragma unroll
        for (int k = 0; k < 72; k++) s += red[k];
        d_bias2[bo] = biases[bo] - s;
    }
}

// ---------------------------------------------------------------------------
// Kernel 3: grouped 3x3 conv via HMMA + ldmatrix. Staging is now a flat
// 38KB LDG.128 -> swizzled STS.128 copy from the fp16 pixel-major buffer.
// ---------------------------------------------------------------------------
__global__ __launch_bounds__(512, 2) void conv_kernel(float* __restrict__ out) {
    __shared__ __align__(16) __half tile[TROWS*TC*CG];   // 38016 B
    __shared__ float wsm[OG*72];

    int b  = blockIdx.z;
    int g  = blockIdx.y;
    int r0 = blockIdx.x * RSTRIP;
    int tid  = threadIdx.x;
    int lane = tid & 31;
    int wi   = tid >> 5;
    uint32_t sb = smem_u32(tile);

    {
        const float* cb = d_comb + (size_t)(b*O_CH + g*OG) * 72;
        for (int idx = tid; idx < OG*72; idx += 512) wsm[idx] = cb[idx];
    }

    // ---- staging: flat copy, image rows r0-1 .. r0+16 = stored rows r0 .. r0+17 ----
    {
        const uint4* src = d_xh + (size_t)(b*G + g) * SLAB + (size_t)r0 * TC;
        #pragma unroll
        for (int k = 0; k < 5; k++) {
            int e = tid + k * 512;
            if (e < TROWS*TC) {
                uint4 v = src[e];
                sts128(sb + SW((uint32_t)e)*16u, v.x, v.y, v.z, v.w);
            }
        }
    }
    __syncthreads();

    // ---- B fragments (weights) ----
    int gid = lane >> 2;
    int tg  = lane & 3;
    uint32_t bf[9];
    {
        const float* wn = wsm + gid * 72 + (tg * 2) * 9;
        #pragma unroll
        for (int j = 0; j < 4; j++) {
            bf[2*j + 0] = pkh2(wn[2*j],     wn[9 + 2*j]);
            bf[2*j + 1] = pkh2(wn[2*j + 1], wn[9 + 2*j + 1]);
        }
        bf[8] = pkh2(wn[8], wn[17]);
    }

    // ---- per-thread ldmatrix base offsets (16B units, before swizzle) ----
    int q  = lane >> 3;
    int l8 = lane & 7;
    int base_j[4], base_8;
    #pragma unroll
    for (int j = 0; j < 4; j++) {
        int t = 2*j + (q >> 1);
        base_j[j] = (wi + t/3)*TC + (q & 1)*8 + l8 + (t % 3);
    }
    base_8 = (wi + 2)*TC + (q & 1)*8 + l8 + 2;

    float bia0 = d_bias2[b*O_CH + g*OG + tg*2];
    float bia1 = d_bias2[b*O_CH + g*OG + tg*2 + 1];

    int hrow = r0 + wi;
    float* obase = out + (size_t)(b*O_CH + g*OG + tg*2) * HW + (size_t)hrow * W;

    #pragma unroll
    for (int ws = 0; ws < 8; ws++) {
        int w16 = ws * 16;
        float d0 = 0.f, d1 = 0.f, d2 = 0.f, d3 = 0.f;

        #pragma unroll
        for (int j = 0; j < 4; j++) {
            uint32_t a16 = (uint32_t)(base_j[j] + w16);
            uint32_t addr = sb + SW(a16)*16u;
            uint32_t a0, a1, a2, a3;
            asm volatile("ldmatrix.sync.aligned.m8n8.x4.shared.b16 {%0,%1,%2,%3}, [%4];"
                         : "=r"(a0), "=r"(a1), "=r"(a2), "=r"(a3) : "r"(addr));
            asm volatile(
                "mma.sync.aligned.m16n8k16.row.col.f32.f16.f16.f32 "
                "{%0,%1,%2,%3},{%4,%5,%6,%7},{%8,%9},{%0,%1,%2,%3};"
                : "+f"(d0), "+f"(d1), "+f"(d2), "+f"(d3)
                : "r"(a0), "r"(a1), "r"(a2), "r"(a3),
                  "r"(bf[2*j]), "r"(bf[2*j + 1]));
        }
        {
            uint32_t a16 = (uint32_t)(base_8 + w16);
            uint32_t addr = sb + SW(a16)*16u;
            uint32_t a0, a1;
            asm volatile("ldmatrix.sync.aligned.m8n8.x2.shared.b16 {%0,%1}, [%2];"
                         : "=r"(a0), "=r"(a1) : "r"(addr));
            asm volatile(
                "mma.sync.aligned.m16n8k8.row.col.f32.f16.f16.f32 "
                "{%0,%1,%2,%3},{%4,%5},{%6},{%0,%1,%2,%3};"
                : "+f"(d0), "+f"(d1), "+f"(d2), "+f"(d3)
                : "r"(a0), "r"(a1), "r"(bf[8]));
        }

        float* ob = obase + w16 + gid;
        ob[0]      = d0 + bia0;
        ob[HW]     = d1 + bia1;
        ob[8]      = d2 + bia0;
        ob[HW + 8] = d3 + bia1;
    }
}

// ---------------------------------------------------------------------------
extern "C" void kernel_launch(void* const* d_in, const int* in_sizes, int n_in,
                              void* d_out, int out_size) {
    const float* x      = (const float*)d_in[0];
    const float* dw     = (const float*)d_in[1];
    const float* pw     = (const float*)d_in[2];
    const float* biases = (const float*)d_in[3];
    float* out = (float*)d_out;

    transform_kernel<<<B*G, 512>>>(x);
    combine_kernel<<<B*O_CH, 72>>>(dw, pw, biases);
    conv_kernel<<<dim3(H/RSTRIP, G, B), 512>>>(out);
}